// round 3
// baseline (speedup 1.0000x reference)
#include <cuda_runtime.h>
#include <stdint.h>

#define N_SENS 10000
#define N_HID  400000
#define N_MOT  1000
#define E_SH   4000000
#define E_HH   16000000
#define E_HM   400000

#define SENS_WORDS 313      // ceil(10000/32)
#define HID_WORDS  12500    // 400000/32

#define GRID 444            // 148 SMs x 3 blocks
#define TPB  512
#define NTHREADS (GRID * TPB)

#define G_SH (E_SH / 4)     // 1,000,000 int4-groups
#define G_HH (E_HH / 4)     // 4,000,000
#define G_HM (E_HM / 4)     // 100,000

// Scratch (__device__ globals; allocation-free rule)
__device__ uint32_t g_sens_bits[SENS_WORDS];
__device__ uint32_t g_hid_bits[HID_WORDS];
__device__ float    g_hid_in[N_HID];
__device__ float    g_hid_spk[N_HID];
__device__ float    g_mot_in[N_MOT];
// Monotonic ticket barrier counters (zero-initialized once at module load;
// never reset — tickets grow across graph replays, target = (ticket/G+1)*G).
__device__ unsigned long long g_bar[4];

__device__ __forceinline__ void grid_barrier(int idx) {
    __syncthreads();
    if (threadIdx.x == 0) {
        __threadfence();
        unsigned long long ticket = atomicAdd(&g_bar[idx], 1ULL);
        unsigned long long target = (ticket / GRID + 1ULL) * GRID;
        while (*(volatile unsigned long long*)&g_bar[idx] < target) { }
        __threadfence();
    }
    __syncthreads();
}

__global__ void __launch_bounds__(TPB, 3)
snn_fused(const float* __restrict__ s_in,
          const float* __restrict__ s_mem,
          const float* __restrict__ h_mem,
          const float* __restrict__ m_mem,
          const float* __restrict__ prev_spk,
          const float4* __restrict__ w_sh,
          const float4* __restrict__ w_hh,
          const float4* __restrict__ w_hm,
          const int4* __restrict__ sh_pre,
          const int4* __restrict__ sh_post,
          const int4* __restrict__ hh_pre,
          const int4* __restrict__ hh_post,
          const int4* __restrict__ hm_pre,
          const int4* __restrict__ hm_post,
          float* __restrict__ out) {
    extern __shared__ uint32_t hb[];          // HID_WORDS words (50 KB)
    __shared__ uint32_t sb[SENS_WORDS];

    const int tid = blockIdx.x * blockDim.x + threadIdx.x;

    // ---------------- P0: zero accumulators, build spike bitmasks -----------
    // 400128 = multiple of 32 so every iterated warp is full (safe ballot)
    for (int i = tid; i < 400128; i += NTHREADS) {
        if (i < N_HID) g_hid_in[i] = 0.0f;
        if (i < N_MOT) g_mot_in[i] = 0.0f;

        int predh = (i < N_HID) ? (prev_spk[i] != 0.0f) : 0;
        uint32_t bitsh = __ballot_sync(0xFFFFFFFFu, predh);
        if ((i & 31) == 0 && (i >> 5) < HID_WORDS) g_hid_bits[i >> 5] = bitsh;

        if (i < 10016) {  // covers SENS_WORDS*32, multiple of 32
            int preds = 0;
            if (i < N_SENS) {
                float m = 0.9f * s_mem[i] + 5.0f * s_in[i];
                preds = (m > 1.0f);
            }
            uint32_t bitss = __ballot_sync(0xFFFFFFFFu, preds);
            if ((i & 31) == 0 && (i >> 5) < SENS_WORDS) g_sens_bits[i >> 5] = bitss;
        }
    }

    grid_barrier(0);

    // Stage bitmasks into shared memory (per block)
    for (int i = threadIdx.x; i < HID_WORDS; i += blockDim.x) hb[i] = g_hid_bits[i];
    for (int i = threadIdx.x; i < SENS_WORDS; i += blockDim.x) sb[i] = g_sens_bits[i];
    __syncthreads();

    // ---------------- P1: SH + HH edges -> g_hid_in (atomics) ---------------
    for (int t = tid; t < G_SH + G_HH; t += NTHREADS) {
        if (t < G_SH) {
            int4 p = __ldcs(&sh_pre[t]);
            uint32_t b0 = (sb[p.x >> 5] >> (p.x & 31)) & 1u;
            uint32_t b1 = (sb[p.y >> 5] >> (p.y & 31)) & 1u;
            uint32_t b2 = (sb[p.z >> 5] >> (p.z & 31)) & 1u;
            uint32_t b3 = (sb[p.w >> 5] >> (p.w & 31)) & 1u;
            int4 q = __ldcs(&sh_post[t]);
            float4 wv = __ldcs(&w_sh[t]);
            if (b0) atomicAdd(&g_hid_in[q.x], wv.x);
            if (b1) atomicAdd(&g_hid_in[q.y], wv.y);
            if (b2) atomicAdd(&g_hid_in[q.z], wv.z);
            if (b3) atomicAdd(&g_hid_in[q.w], wv.w);
        } else {
            int e = t - G_SH;
            int4 p = __ldcs(&hh_pre[e]);
            uint32_t b0 = (hb[p.x >> 5] >> (p.x & 31)) & 1u;
            uint32_t b1 = (hb[p.y >> 5] >> (p.y & 31)) & 1u;
            uint32_t b2 = (hb[p.z >> 5] >> (p.z & 31)) & 1u;
            uint32_t b3 = (hb[p.w >> 5] >> (p.w & 31)) & 1u;
            if ((b0 | b1 | b2 | b3) == 0u) continue;
            int4 q = __ldcs(&hh_post[e]);
            float4 wv = __ldcs(&w_hh[e]);
            if (b0) atomicAdd(&g_hid_in[q.x], 0.5f * wv.x);
            if (b1) atomicAdd(&g_hid_in[q.y], 0.5f * wv.y);
            if (b2) atomicAdd(&g_hid_in[q.z], 0.5f * wv.z);
            if (b3) atomicAdd(&g_hid_in[q.w], 0.5f * wv.w);
        }
    }

    grid_barrier(1);

    // ---------------- P2: hidden LIF -> g_hid_spk ---------------------------
    {
        const float4* hm4 = (const float4*)h_mem;
        const float4* hi4 = (const float4*)g_hid_in;
        float4* hs4 = (float4*)g_hid_spk;
        for (int i = tid; i < N_HID / 4; i += NTHREADS) {
            float4 m = __ldg(&hm4[i]);
            float4 a = hi4[i];
            float4 s;
            s.x = (0.9f * m.x + 5.0f * a.x > 1.0f) ? 1.0f : 0.0f;
            s.y = (0.9f * m.y + 5.0f * a.y > 1.0f) ? 1.0f : 0.0f;
            s.z = (0.9f * m.z + 5.0f * a.z > 1.0f) ? 1.0f : 0.0f;
            s.w = (0.9f * m.w + 5.0f * a.w > 1.0f) ? 1.0f : 0.0f;
            hs4[i] = s;
        }
    }

    grid_barrier(2);

    // ---------------- P3: HM edges -> g_mot_in ------------------------------
    for (int t = tid; t < G_HM; t += NTHREADS) {
        int4 p = __ldcs(&hm_pre[t]);
        float s0 = g_hid_spk[p.x];
        float s1 = g_hid_spk[p.y];
        float s2 = g_hid_spk[p.z];
        float s3 = g_hid_spk[p.w];
        if (s0 == 0.0f && s1 == 0.0f && s2 == 0.0f && s3 == 0.0f) continue;
        int4 q = __ldcs(&hm_post[t]);
        float4 wv = __ldcs(&w_hm[t]);
        if (s0 != 0.0f) atomicAdd(&g_mot_in[q.x], wv.x);
        if (s1 != 0.0f) atomicAdd(&g_mot_in[q.y], wv.y);
        if (s2 != 0.0f) atomicAdd(&g_mot_in[q.z], wv.z);
        if (s3 != 0.0f) atomicAdd(&g_mot_in[q.w], wv.w);
    }

    grid_barrier(3);

    // ---------------- P4: motor LIF -> out ----------------------------------
    for (int i = tid; i < N_MOT; i += NTHREADS) {
        float m = 0.9f * __ldg(&m_mem[i]) + 20.0f * g_mot_in[i];
        out[i] = (m > 1.0f) ? 1.0f : 0.0f;
    }
}

extern "C" void kernel_launch(void* const* d_in, const int* in_sizes, int n_in,
                              void* d_out, int out_size) {
    const float* sensory_input     = (const float*)d_in[0];
    const float* sensory_mem       = (const float*)d_in[1];
    const float* hidden_mem        = (const float*)d_in[2];
    const float* motor_mem         = (const float*)d_in[3];
    const float* hidden_prev_spike = (const float*)d_in[4];
    const float* w_sh              = (const float*)d_in[5];
    const float* w_hh              = (const float*)d_in[6];
    const float* w_hm              = (const float*)d_in[7];
    const int*   sh_pre            = (const int*)d_in[8];
    const int*   sh_post           = (const int*)d_in[9];
    const int*   hh_pre            = (const int*)d_in[10];
    const int*   hh_post           = (const int*)d_in[11];
    const int*   hm_pre            = (const int*)d_in[12];
    const int*   hm_post           = (const int*)d_in[13];
    float* out = (float*)d_out;

    const int smem = HID_WORDS * sizeof(uint32_t);  // 50000 B dynamic
    cudaFuncSetAttribute(snn_fused, cudaFuncAttributeMaxDynamicSharedMemorySize,
                         smem);

    snn_fused<<<GRID, TPB, smem>>>(
        sensory_input, sensory_mem, hidden_mem, motor_mem, hidden_prev_spike,
        (const float4*)w_sh, (const float4*)w_hh, (const float4*)w_hm,
        (const int4*)sh_pre, (const int4*)sh_post,
        (const int4*)hh_pre, (const int4*)hh_post,
        (const int4*)hm_pre, (const int4*)hm_post,
        out);
}